// round 10
// baseline (speedup 1.0000x reference)
#include <cuda_runtime.h>
#include <cuda_bf16.h>
#include <cstdint>

#define BATCH 4
#define SEQL 512
#define TOK (BATCH*SEQL)
#define DM 1536
#define DIP 6448
#define DI 3072
#define CONVD 3328
#define NH 48
#define HD 64
#define DS 128
#define NL 4
#define KC 4
#define FEATD 1552
#define EPSV 1e-5f

// ---------------- workspace ----------------
__device__ float g_h[TOK*DM];
__device__ float g_x[TOK*DM];
__device__ float g_zx[TOK*DIP];
__device__ float g_xBC[TOK*CONVD];
__device__ float g_dt[TOK*NH];
__device__ float g_y[TOK*DI];
__device__ float g_feat[BATCH*FEATD];
__device__ __nv_bfloat16 g_wihi[NL*DIP*DM];
__device__ __nv_bfloat16 g_wilo[NL*DIP*DM];
__device__ __nv_bfloat16 g_wohi[NL*DM*DI];
__device__ __nv_bfloat16 g_wolo[NL*DM*DI];
__device__ __nv_bfloat16 g_ahi[TOK*DI];
__device__ __nv_bfloat16 g_alo[TOK*DI];

// ================= helpers =================
__device__ __forceinline__ uint32_t smem_u32(const void* p) {
    uint32_t a;
    asm("{ .reg .u64 t; cvta.to.shared.u64 t, %1; cvt.u32.u64 %0, t; }" : "=r"(a) : "l"(p));
    return a;
}
__device__ __forceinline__ void ldm4(uint32_t* r, uint32_t addr) {
    asm volatile("ldmatrix.sync.aligned.m8n8.x4.shared.b16 {%0,%1,%2,%3}, [%4];"
                 : "=r"(r[0]), "=r"(r[1]), "=r"(r[2]), "=r"(r[3]) : "r"(addr));
}
__device__ __forceinline__ void mma16816(float* c, const uint32_t* a, uint32_t b0, uint32_t b1) {
    asm volatile("mma.sync.aligned.m16n8k16.row.col.f32.bf16.bf16.f32 "
                 "{%0,%1,%2,%3}, {%4,%5,%6,%7}, {%8,%9}, {%0,%1,%2,%3};"
                 : "+f"(c[0]), "+f"(c[1]), "+f"(c[2]), "+f"(c[3])
                 : "r"(a[0]), "r"(a[1]), "r"(a[2]), "r"(a[3]), "r"(b0), "r"(b1));
}
__device__ __forceinline__ void cp16(uint32_t dst, const void* src, int sz) {
    asm volatile("cp.async.cg.shared.global [%0], [%1], 16, %2;"
                 :: "r"(dst), "l"(src), "r"(sz) : "memory");
}
__device__ __forceinline__ void cp4(uint32_t dst, const void* src) {
    asm volatile("cp.async.ca.shared.global [%0], [%1], 4;"
                 :: "r"(dst), "l"(src) : "memory");
}
#define CP_COMMIT() asm volatile("cp.async.commit_group;" ::: "memory")
#define CP_WAIT3()  asm volatile("cp.async.wait_group 3;" ::: "memory")
#define CP_WAIT1()  asm volatile("cp.async.wait_group 1;" ::: "memory")
#define CP_WAIT0()  asm volatile("cp.async.wait_group 0;" ::: "memory")

__device__ __forceinline__ void split2(float x, float y, uint32_t& h, uint32_t& l) {
    __nv_bfloat162 hh = __floats2bfloat162_rn(x, y);
    float2 f = __bfloat1622float2(hh);
    __nv_bfloat162 ll = __floats2bfloat162_rn(x - f.x, y - f.y);
    h = *(uint32_t*)&hh; l = *(uint32_t*)&ll;
}

// ---------------- fused weight split ----------------
#define NIN4 ((long)NL*DIP*DM/4)
#define NOUT4 ((long)NL*DM*DI/4)
__global__ void k_split_all(const float4* __restrict__ wi, const float4* __restrict__ wo,
                            uint2* __restrict__ wihi, uint2* __restrict__ wilo,
                            uint2* __restrict__ wohi, uint2* __restrict__ wolo) {
    long i = (long)blockIdx.x * blockDim.x + threadIdx.x;
    const float4* src; uint2 *hi, *lo; long idx;
    if (i < NIN4) { src = wi; hi = wihi; lo = wilo; idx = i; }
    else if (i < NIN4 + NOUT4) { src = wo; hi = wohi; lo = wolo; idx = i - NIN4; }
    else return;
    float4 v = src[idx];
    uint2 h, l;
    split2(v.x, v.y, h.x, l.x);
    split2(v.z, v.w, h.y, l.y);
    hi[idx] = h; lo[idx] = l;
}

// ============ split-bf16 HMMA GEMM (R7 winner config) ============
#define SA_HI 0
#define SA_LO (128*64)
#define SB_HI (2*128*64)
#define SB_LO (2*128*64 + 64*64)
#define STAGE (2*128*64 + 2*64*64)     // 24576 B
#define GEMM_SMEM (2*STAGE)            // 49152 B

__global__ void __launch_bounds__(128, 4) k_gemm_mma(
        const __nv_bfloat16* __restrict__ Ahi, const __nv_bfloat16* __restrict__ Alo,
        const __nv_bfloat16* __restrict__ Bhi, const __nv_bfloat16* __restrict__ Blo,
        float* __restrict__ C, int N, int K, int beta) {
    extern __shared__ __align__(16) char smem[];
    int tid = threadIdx.x;
    int wid = tid >> 5, lane = tid & 31;
    int m0 = blockIdx.x * 128;
    int n0 = blockIdx.y * 64;
    int wm = wid & 1;
    int wn = wid >> 1;
    uint32_t sb = smem_u32(smem);

    float acc[4][4][4];
#pragma unroll
    for (int i = 0; i < 4; i++)
#pragma unroll
        for (int j = 0; j < 4; j++)
#pragma unroll
            for (int q = 0; q < 4; q++) acc[i][j][q] = 0.f;

    int rbA = wm*64 + (lane & 15);
    int lcA = lane >> 4;
    int swA = (rbA >> 1) & 3;
    int rbB = wn*32 + (lane & 7) + ((lane >> 4) & 1) * 8;
    int lcB = (lane >> 3) & 1;
    int swB = (rbB >> 1) & 3;

    const int NK = K >> 5;

    auto issue = [&](int kc) {
        uint32_t stg = sb + (uint32_t)(kc & 1) * STAGE;
        size_t kbyte = (size_t)(kc << 5) * 2;
#pragma unroll
        for (int j = 0; j < 4; j++) {
            int idx = (j << 7) + tid;
            int r = idx >> 2, c = idx & 3;
            int cs = c ^ ((r >> 1) & 3);
            size_t arow = ((size_t)(m0 + r) * K) * 2 + kbyte + c*16;
            cp16(stg + SA_HI + r*64 + cs*16, (const char*)Ahi + arow, 16);
            cp16(stg + SA_LO + r*64 + cs*16, (const char*)Alo + arow, 16);
        }
#pragma unroll
        for (int j = 0; j < 2; j++) {
            int idx = (j << 7) + tid;
            int r = idx >> 2, c = idx & 3;
            int cs = c ^ ((r >> 1) & 3);
            int bn = n0 + r;
            int ok = (bn < N) ? 16 : 0;
            int bnc = (bn < N) ? bn : (N - 1);
            size_t brow = ((size_t)bnc * K) * 2 + kbyte + c*16;
            cp16(stg + SB_HI + r*64 + cs*16, (const char*)Bhi + brow, ok);
            cp16(stg + SB_LO + r*64 + cs*16, (const char*)Blo + brow, ok);
        }
        CP_COMMIT();
    };

    issue(0);

    for (int kc = 0; kc < NK; kc++) {
        if (kc + 1 < NK) { issue(kc + 1); CP_WAIT1(); }
        else            { CP_WAIT0(); }
        __syncthreads();
        uint32_t stg = sb + (uint32_t)(kc & 1) * STAGE;
#pragma unroll
        for (int kk = 0; kk < 2; kk++) {
            uint32_t czA = (uint32_t)((((kk << 1) | lcA) ^ swA) * 16);
            uint32_t czB = (uint32_t)((((kk << 1) | lcB) ^ swB) * 16);
            uint32_t adrAhi = stg + SA_HI + (uint32_t)rbA*64 + czA;
            uint32_t adrAlo = stg + SA_LO + (uint32_t)rbA*64 + czA;
            uint32_t adrBhi = stg + SB_HI + (uint32_t)rbB*64 + czB;
            uint32_t adrBlo = stg + SB_LO + (uint32_t)rbB*64 + czB;
            uint32_t fa[4][4], fb[2][4], fbl[2][4];
#pragma unroll
            for (int mt = 0; mt < 4; mt++) ldm4(fa[mt], adrAhi + mt*16*64);
#pragma unroll
            for (int bt = 0; bt < 2; bt++) ldm4(fb[bt], adrBhi + bt*16*64);
#pragma unroll
            for (int mt = 0; mt < 4; mt++)
#pragma unroll
                for (int nt = 0; nt < 4; nt++)
                    mma16816(acc[mt][nt], fa[mt], fb[nt>>1][(nt&1)*2], fb[nt>>1][(nt&1)*2+1]);
#pragma unroll
            for (int bt = 0; bt < 2; bt++) ldm4(fbl[bt], adrBlo + bt*16*64);
#pragma unroll
            for (int mt = 0; mt < 4; mt++)
#pragma unroll
                for (int nt = 0; nt < 4; nt++)
                    mma16816(acc[mt][nt], fa[mt], fbl[nt>>1][(nt&1)*2], fbl[nt>>1][(nt&1)*2+1]);
#pragma unroll
            for (int mt = 0; mt < 4; mt++) ldm4(fa[mt], adrAlo + mt*16*64);
#pragma unroll
            for (int mt = 0; mt < 4; mt++)
#pragma unroll
                for (int nt = 0; nt < 4; nt++)
                    mma16816(acc[mt][nt], fa[mt], fb[nt>>1][(nt&1)*2], fb[nt>>1][(nt&1)*2+1]);
        }
        __syncthreads();
    }

    int mbase = m0 + wm*64 + (lane >> 2);
    int nbase = n0 + wn*32 + (lane & 3)*2;
#pragma unroll
    for (int mt = 0; mt < 4; mt++) {
#pragma unroll
        for (int nt = 0; nt < 4; nt++) {
            int n = nbase + nt*8;
            if (n < N) {
                int m = mbase + mt*16;
                float2 v0 = make_float2(acc[mt][nt][0], acc[mt][nt][1]);
                float2 v1 = make_float2(acc[mt][nt][2], acc[mt][nt][3]);
                float* p0 = &C[(size_t)m * N + n];
                float* p1 = &C[(size_t)(m + 8) * N + n];
                if (beta) {
                    float2 o0 = *(float2*)p0, o1 = *(float2*)p1;
                    v0.x += o0.x; v0.y += o0.y; v1.x += o1.x; v1.y += o1.y;
                }
                *(float2*)p0 = v0;
                *(float2*)p1 = v1;
            }
        }
    }
}

// ---------------- embedding gather (float4) ----------------
__global__ void k_embed(const int* __restrict__ ids, const float* __restrict__ emb,
                        float* __restrict__ h) {
    int i = blockIdx.x * blockDim.x + threadIdx.x;
    if (i >= TOK*DM/4) return;
    int t = i / (DM/4), d4 = i % (DM/4);
    ((float4*)h)[i] = ((const float4*)emb)[(long)ids[t]*(DM/4) + d4];
}

// ---------------- rmsnorm -> bf16 hi/lo (float4) ----------------
__global__ void k_rmsnorm_split(const float* __restrict__ in, const float* __restrict__ w,
                                __nv_bfloat16* __restrict__ ohi, __nv_bfloat16* __restrict__ olo,
                                int D) {
    int row = blockIdx.x;
    const float4* x4 = (const float4*)(in + (long)row*D);
    int nd4 = D >> 2;
    float ss = 0.f;
    for (int d = threadIdx.x; d < nd4; d += blockDim.x) {
        float4 v = x4[d];
        ss += v.x*v.x + v.y*v.y + v.z*v.z + v.w*v.w;
    }
    __shared__ float red[32];
    for (int o = 16; o; o >>= 1) ss += __shfl_down_sync(0xffffffffu, ss, o);
    if ((threadIdx.x & 31) == 0) red[threadIdx.x >> 5] = ss;
    __syncthreads();
    if (threadIdx.x < 32) {
        float v = (threadIdx.x < (blockDim.x >> 5)) ? red[threadIdx.x] : 0.f;
        for (int o = 16; o; o >>= 1) v += __shfl_down_sync(0xffffffffu, v, o);
        if (threadIdx.x == 0) red[0] = rsqrtf(v / (float)D + EPSV);
    }
    __syncthreads();
    float s = red[0];
    const float4* w4 = (const float4*)w;
    uint2* h2 = (uint2*)(ohi + (long)row*D);
    uint2* l2 = (uint2*)(olo + (long)row*D);
    for (int d = threadIdx.x; d < nd4; d += blockDim.x) {
        float4 v = x4[d], ww = w4[d];
        v.x *= s*ww.x; v.y *= s*ww.y; v.z *= s*ww.z; v.w *= s*ww.w;
        uint2 h, l;
        split2(v.x, v.y, h.x, l.x);
        split2(v.z, v.w, h.y, l.y);
        h2[d] = h; l2[d] = l;
    }
}

// ---------------- plain rmsnorm (final, float4) ----------------
__global__ void k_rmsnorm(const float* __restrict__ in, const float* __restrict__ w,
                          float* __restrict__ out, int D) {
    int row = blockIdx.x;
    const float4* x4 = (const float4*)(in + (long)row*D);
    int nd4 = D >> 2;
    float ss = 0.f;
    for (int d = threadIdx.x; d < nd4; d += blockDim.x) {
        float4 v = x4[d];
        ss += v.x*v.x + v.y*v.y + v.z*v.z + v.w*v.w;
    }
    __shared__ float red[32];
    for (int o = 16; o; o >>= 1) ss += __shfl_down_sync(0xffffffffu, ss, o);
    if ((threadIdx.x & 31) == 0) red[threadIdx.x >> 5] = ss;
    __syncthreads();
    if (threadIdx.x < 32) {
        float v = (threadIdx.x < (blockDim.x >> 5)) ? red[threadIdx.x] : 0.f;
        for (int o = 16; o; o >>= 1) v += __shfl_down_sync(0xffffffffu, v, o);
        if (threadIdx.x == 0) red[0] = rsqrtf(v / (float)D + EPSV);
    }
    __syncthreads();
    float s = red[0];
    const float4* w4 = (const float4*)w;
    float4* o4 = (float4*)(out + (long)row*D);
    for (int d = threadIdx.x; d < nd4; d += blockDim.x) {
        float4 v = x4[d], ww = w4[d];
        v.x *= s*ww.x; v.y *= s*ww.y; v.z *= s*ww.z; v.w *= s*ww.w;
        o4[d] = v;
    }
}

// ---------------- fused conv+silu (float4 channels) and dt=softplus ----------------
#define CONVD4 (CONVD/4)
__global__ void k_convdt(const float* __restrict__ zx, const float* __restrict__ w,
                         const float* __restrict__ bconv, const float* __restrict__ dtb,
                         float* __restrict__ xBC, float* __restrict__ dtout) {
    int i = blockIdx.x * blockDim.x + threadIdx.x;
    if (i < TOK*CONVD4) {
        int c4 = i % CONVD4;
        int t = i / CONVD4;
        int s = t % SEQL;
        const float* srcb = zx + (long)t*DIP + DI + c4*4;
        const float4* w4 = (const float4*)w + c4*4 + 0;   // w[c][0..3] is one float4 per channel
        float4 acc = ((const float4*)bconv)[c4];
        float4 wv0 = ((const float4*)w)[c4*4 + 0];
        float4 wv1 = ((const float4*)w)[c4*4 + 1];
        float4 wv2 = ((const float4*)w)[c4*4 + 2];
        float4 wv3 = ((const float4*)w)[c4*4 + 3];
        (void)w4;
#pragma unroll
        for (int k = 0; k < KC; k++) {
            int ss = s - (KC-1) + k;
            if (ss >= 0) {
                float4 xv = *(const float4*)(srcb + (long)(ss - s) * DIP);
                float k0 = (&wv0.x)[k], k1 = (&wv1.x)[k], k2 = (&wv2.x)[k], k3 = (&wv3.x)[k];
                acc.x += k0 * xv.x;
                acc.y += k1 * xv.y;
                acc.z += k2 * xv.z;
                acc.w += k3 * xv.w;
            }
        }
        acc.x = acc.x / (1.f + expf(-acc.x));
        acc.y = acc.y / (1.f + expf(-acc.y));
        acc.z = acc.z / (1.f + expf(-acc.z));
        acc.w = acc.w / (1.f + expf(-acc.w));
        ((float4*)xBC)[i] = acc;
    } else {
        int j = i - TOK*CONVD4;
        if (j >= TOK*NH) return;
        int h = j % NH, t = j / NH;
        float v = zx[(long)t*DIP + DI + CONVD + h] + dtb[h];
        dtout[j] = (v > 20.f) ? v : log1pf(expf(v));
    }
}

// ---------------- SSD scan: 2 heads/CTA (96 CTAs = 1 wave), shared B/C ----------------
// stage floats: B0:0 C0:128 B1:256 C1:384 | x[h0s0]:512 x[h0s1]:576 x[h1s0]:640 x[h1s1]:704
//               dt[h0s0,h0s1,h1s0,h1s1]:768..771  pad -> 784
#define SC_STGF 784
#define SC_STGB (SC_STGF*4)
__global__ void __launch_bounds__(512, 1) k_scan(
        const float* __restrict__ xBC, const float* __restrict__ dt,
        const float* __restrict__ A_log, const float* __restrict__ Dvec,
        float* __restrict__ y) {
    int b = blockIdx.x / (NH/2);
    int h0 = (blockIdx.x % (NH/2)) * 2;
    int tid = threadIdx.x;
    int hh = tid >> 8;           // 0/1: which head this thread computes
    int l = tid & 255;
    int pi = l >> 4;             // 0..15 -> p rows pi*4..+3
    int ni = l & 15;             // 0..15 -> n cols ni*8..+7
    int h = h0 + hh;
    float A = -expf(A_log[h]);
    float Dh = Dvec[h];

    __shared__ __align__(16) float ring[4*SC_STGF];
    uint32_t rb = smem_u32(ring);
    const float* base = xBC + (long)b*SEQL*CONVD;
    const float* dbase = dt + ((long)b*SEQL)*NH + h0;

    float st[4][8];
#pragma unroll
    for (int i = 0; i < 4; i++)
#pragma unroll
        for (int j = 0; j < 8; j++) st[i][j] = 0.f;

    auto issue = [&](int s) {
        uint32_t sa = rb + (uint32_t)(s & 3) * SC_STGB;
        const float* r0 = base + (long)(2*s) * CONVD;
        const float* r1 = r0 + CONVD;
        if (tid < 32)        cp16(sa +            tid*16,        r0 + DI + tid*4, 16);            // B0
        else if (tid < 64)   cp16(sa + 512  + (tid-32)*16,       r0 + DI + DS + (tid-32)*4, 16);  // C0
        else if (tid < 96)   cp16(sa + 1024 + (tid-64)*16,       r1 + DI + (tid-64)*4, 16);       // B1
        else if (tid < 128)  cp16(sa + 1536 + (tid-96)*16,       r1 + DI + DS + (tid-96)*4, 16);  // C1
        else if (tid < 144)  cp16(sa + 2048 + (tid-128)*16,      r0 + h0*HD + (tid-128)*4, 16);   // x h0 s0
        else if (tid < 160)  cp16(sa + 2304 + (tid-144)*16,      r1 + h0*HD + (tid-144)*4, 16);   // x h0 s1
        else if (tid < 176)  cp16(sa + 2560 + (tid-160)*16,      r0 + (h0+1)*HD + (tid-160)*4, 16); // x h1 s0
        else if (tid < 192)  cp16(sa + 2816 + (tid-176)*16,      r1 + (h0+1)*HD + (tid-176)*4, 16); // x h1 s1
        else if (tid == 192) cp4(sa + 3072, dbase + (long)(2*s)*NH);
        else if (tid == 193) cp4(sa + 3076, dbase + (long)(2*s+1)*NH);
        else if (tid == 194) cp4(sa + 3080, dbase + (long)(2*s)*NH + 1);
        else if (tid == 195) cp4(sa + 3084, dbase + (long)(2*s+1)*NH + 1);
        CP_COMMIT();
    };

    issue(0); issue(1); issue(2); issue(3);

    const int NPAIR = SEQL/2;
    for (int s = 0; s < NPAIR; s++) {
        CP_WAIT3();
        __syncthreads();
        const float* stg = ring + (s & 3) * SC_STGF;
#pragma unroll
        for (int half = 0; half < 2; half++) {
            int t = 2*s + half;
            float dtt = stg[768 + hh*2 + half];
            float decay = expf(dtt * A);
            const float* Bp = stg + half*256;
            const float* Cp = Bp + 128;
            float Bv[8], Cv[8];
#pragma unroll
            for (int j = 0; j < 8; j += 4) {
                float4 bb = *(const float4*)&Bp[ni*8 + j];
                Bv[j] = bb.x; Bv[j+1] = bb.y; Bv[j+2] = bb.z; Bv[j+3] = bb.w;
                float4 cc = *(const float4*)&Cp[ni*8 + j];
                Cv[j] = cc.x; Cv[j+1] = cc.y; Cv[j+2] = cc.z; Cv[j+3] = cc.w;
            }
            float dtB[8];
#pragma unroll
            for (int j = 0; j < 8; j++) dtB[j] = dtt * Bv[j];
            const float* xp = stg + 512 + hh*128 + half*64;
            float vout[4];
#pragma unroll
            for (int pp = 0; pp < 4; pp++) {
                float xv = xp[pi*4 + pp];
                float a = 0.f;
#pragma unroll
                for (int j = 0; j < 8; j++) {
                    st[pp][j] = st[pp][j] * decay + xv * dtB[j];
                    a += st[pp][j] * Cv[j];
                }
                a += __shfl_down_sync(0xffffffffu, a, 8, 16);
                a += __shfl_down_sync(0xffffffffu, a, 4, 16);
                a += __shfl_down_sync(0xffffffffu, a, 2, 16);
                a += __shfl_down_sync(0xffffffffu, a, 1, 16);
                vout[pp] = a + Dh * xv;
            }
            if (ni == 0) {
                float4 v = make_float4(vout[0], vout[1], vout[2], vout[3]);
                *(float4*)&y[((long)b*SEQL + t)*DI + h*HD + pi*4] = v;
            }
        }
        __syncthreads();
        if (s + 4 < NPAIR) issue(s + 4);
        else CP_COMMIT();
    }
}

// ---------------- y = rmsnorm(y * silu(z)) * w -> bf16 hi/lo (float4) ----------------
__global__ void k_gatenorm_split(const float* __restrict__ yin, const float* __restrict__ zx,
                                 const float* __restrict__ w,
                                 __nv_bfloat16* __restrict__ ohi, __nv_bfloat16* __restrict__ olo) {
    int row = blockIdx.x;
    const float4* yr = (const float4*)(yin + (long)row*DI);
    const float4* zr = (const float4*)(zx + (long)row*DIP);
    __shared__ __align__(16) float sv[DI];
    float ss = 0.f;
    const int nd4 = DI >> 2;
    for (int d = threadIdx.x; d < nd4; d += blockDim.x) {
        float4 zv = zr[d], yv = yr[d];
        float4 v;
        v.x = yv.x * (zv.x / (1.f + expf(-zv.x)));
        v.y = yv.y * (zv.y / (1.f + expf(-zv.y)));
        v.z = yv.z * (zv.z / (1.f + expf(-zv.z)));
        v.w = yv.w * (zv.w / (1.f + expf(-zv.w)));
        ((float4*)sv)[d] = v;
        ss += v.x*v.x + v.y*v.y + v.z*v.z + v.w*v.w;
    }
    __shared__ float red[32];
    for (int o = 16; o; o >>= 1) ss += __shfl_down_sync(0xffffffffu, ss, o);
    if ((threadIdx.x & 31) == 0) red[threadIdx.x >> 5] = ss;
    __syncthreads();
    if (threadIdx.x < 32) {
        float v = (threadIdx.x < (blockDim.x >> 5)) ? red[threadIdx.x] : 0.f;
        for (int o = 16; o; o >>= 1) v += __shfl_down_sync(0xffffffffu, v, o);
        if (threadIdx.x == 0) red[0] = rsqrtf(v / (float)DI + EPSV);
    }
    __syncthreads();
    float s = red[0];
    const float4* w4 = (const float4*)w;
    uint2* h2 = (uint2*)(ohi + (long)row*DI);
    uint2* l2 = (uint2*)(olo + (long)row*DI);
    for (int d = threadIdx.x; d < nd4; d += blockDim.x) {
        float4 v = ((float4*)sv)[d], ww = w4[d];
        v.x *= s*ww.x; v.y *= s*ww.y; v.z *= s*ww.z; v.w *= s*ww.w;
        uint2 h, l;
        split2(v.x, v.y, h.x, l.x);
        split2(v.z, v.w, h.y, l.y);
        h2[d] = h; l2[d] = l;
    }
}

// ---------------- masked mean pool + cat embed concat ----------------
__global__ void k_pool(const float* __restrict__ x, const int* __restrict__ mask,
                       const int* __restrict__ cats, const float* __restrict__ cat_emb,
                       float* __restrict__ feat) {
    int b = blockIdx.x;
    __shared__ float sm[SEQL];
    __shared__ float minv;
    for (int t = threadIdx.x; t < SEQL; t += blockDim.x)
        sm[t] = (float)mask[b*SEQL + t];
    __syncthreads();
    if (threadIdx.x == 0) {
        float s = 0.f;
        for (int t = 0; t < SEQL; t++) s += sm[t];
        if (s < 1e-9f) s = 1e-9f;
        minv = 1.f / s;
    }
    __syncthreads();
    for (int d = threadIdx.x; d < DM; d += blockDim.x) {
        float acc = 0.f;
        for (int t = 0; t < SEQL; t++)
            acc += sm[t] * x[((long)b*SEQL + t)*DM + d];
        feat[b*FEATD + d] = acc * minv;
    }
    if (threadIdx.x < 16)
        feat[b*FEATD + DM + threadIdx.x] = cat_emb[cats[b]*16 + threadIdx.x];
}

// ---------------- classifier heads ----------------
__global__ void k_heads(const float* __restrict__ feat,
                        const float* __restrict__ qw, const float* __restrict__ qb,
                        const float* __restrict__ aw, const float* __restrict__ ab,
                        float* __restrict__ out) {
    int b = blockIdx.y, j = blockIdx.x;
    const float* w;
    float bias;
    if (j < 21) { w = qw + j*FEATD; bias = qb[j]; }
    else        { w = aw + (j-21)*FEATD; bias = ab[j-21]; }
    float s = 0.f;
    for (int d = threadIdx.x; d < FEATD; d += blockDim.x)
        s += feat[b*FEATD + d] * w[d];
    __shared__ float red[8];
    for (int o = 16; o; o >>= 1) s += __shfl_down_sync(0xffffffffu, s, o);
    if ((threadIdx.x & 31) == 0) red[threadIdx.x >> 5] = s;
    __syncthreads();
    if (threadIdx.x == 0) {
        float v = 0.f;
        for (int i = 0; i < (int)(blockDim.x >> 5); i++) v += red[i];
        out[b*30 + j] = v + bias;
    }
}

// ---------------- host orchestration ----------------
extern "C" void kernel_launch(void* const* d_in, const int* in_sizes, int n_in,
                              void* d_out, int out_size) {
    const int*   ids      = (const int*)d_in[0];
    const int*   mask     = (const int*)d_in[1];
    const int*   cats     = (const int*)d_in[2];
    const float* emb      = (const float*)d_in[3];
    const float* norm_w   = (const float*)d_in[4];
    const float* in_proj  = (const float*)d_in[5];
    const float* conv_w   = (const float*)d_in[6];
    const float* conv_b   = (const float*)d_in[7];
    const float* dt_bias  = (const float*)d_in[8];
    const float* A_log    = (const float*)d_in[9];
    const float* Dvec     = (const float*)d_in[10];
    const float* gnorm_w  = (const float*)d_in[11];
    const float* out_proj = (const float*)d_in[12];
    const float* final_w  = (const float*)d_in[13];
    const float* cat_emb  = (const float*)d_in[14];
    const float* qw       = (const float*)d_in[15];
    const float* qb       = (const float*)d_in[16];
    const float* aw       = (const float*)d_in[17];
    const float* ab       = (const float*)d_in[18];
    float* out = (float*)d_out;

    float *p_h, *p_x, *p_zx, *p_xBC, *p_dt, *p_y, *p_feat;
    __nv_bfloat16 *p_wihi, *p_wilo, *p_wohi, *p_wolo, *p_ahi, *p_alo;
    cudaGetSymbolAddress((void**)&p_h,    g_h);
    cudaGetSymbolAddress((void**)&p_x,    g_x);
    cudaGetSymbolAddress((void**)&p_zx,   g_zx);
    cudaGetSymbolAddress((void**)&p_xBC,  g_xBC);
    cudaGetSymbolAddress((void**)&p_dt,   g_dt);
    cudaGetSymbolAddress((void**)&p_y,    g_y);
    cudaGetSymbolAddress((void**)&p_feat, g_feat);
    cudaGetSymbolAddress((void**)&p_wihi, g_wihi);
    cudaGetSymbolAddress((void**)&p_wilo, g_wilo);
    cudaGetSymbolAddress((void**)&p_wohi, g_wohi);
    cudaGetSymbolAddress((void**)&p_wolo, g_wolo);
    cudaGetSymbolAddress((void**)&p_ahi,  g_ahi);
    cudaGetSymbolAddress((void**)&p_alo,  g_alo);

    cudaFuncSetAttribute(k_gemm_mma, cudaFuncAttributeMaxDynamicSharedMemorySize, GEMM_SMEM);

    {
        long ntot = NIN4 + NOUT4;
        k_split_all<<<(unsigned)((ntot + 255)/256), 256>>>(
            (const float4*)in_proj, (const float4*)out_proj,
            (uint2*)p_wihi, (uint2*)p_wilo, (uint2*)p_wohi, (uint2*)p_wolo);
    }
    {
        int n = TOK*DM/4;
        k_embed<<<(n + 255)/256, 256>>>(ids, emb, p_h);
    }

    for (int l = 0; l < NL; l++) {
        k_rmsnorm_split<<<TOK, 256>>>(p_h, norm_w + l*DM, p_ahi, p_alo, DM);
        {
            dim3 grid(TOK/128, (DIP + 63)/64);
            k_gemm_mma<<<grid, 128, GEMM_SMEM>>>(p_ahi, p_alo,
                                                 p_wihi + (long)l*DIP*DM, p_wilo + (long)l*DIP*DM,
                                                 p_zx, DIP, DM, 0);
        }
        {
            int n = TOK*CONVD4 + TOK*NH;
            k_convdt<<<(n + 255)/256, 256>>>(p_zx, conv_w + (long)l*CONVD*KC,
                                             conv_b + l*CONVD, dt_bias + l*NH,
                                             p_xBC, p_dt);
        }
        k_scan<<<BATCH*(NH/2), 512>>>(p_xBC, p_dt, A_log + l*NH, Dvec + l*NH, p_y);
        k_gatenorm_split<<<TOK, 256>>>(p_y, p_zx, gnorm_w + (long)l*DI, p_ahi, p_alo);
        {
            dim3 grid(TOK/128, DM/64);
            k_gemm_mma<<<grid, 128, GEMM_SMEM>>>(p_ahi, p_alo,
                                                 p_wohi + (long)l*DM*DI, p_wolo + (long)l*DM*DI,
                                                 p_h, DM, DI, 1);
        }
    }

    k_rmsnorm<<<TOK, 256>>>(p_h, final_w, p_x, DM);
    k_pool<<<BATCH, 256>>>(p_x, mask, cats, cat_emb, p_feat);
    {
        dim3 grid(30, BATCH);
        k_heads<<<grid, 128>>>(p_feat, qw, qb, aw, ab, out);
    }
}

// round 11
// speedup vs baseline: 1.1175x; 1.1175x over previous
#include <cuda_runtime.h>
#include <cuda_bf16.h>
#include <cstdint>

#define BATCH 4
#define SEQL 512
#define TOK (BATCH*SEQL)
#define DM 1536
#define DIP 6448
#define DI 3072
#define CONVD 3328
#define NH 48
#define HD 64
#define DS 128
#define NL 4
#define KC 4
#define FEATD 1552
#define EPSV 1e-5f

// ---------------- workspace ----------------
__device__ float g_h[TOK*DM];
__device__ float g_x[TOK*DM];
__device__ float g_zx[TOK*DIP];
__device__ float g_xBC[TOK*CONVD];
__device__ float g_dt[TOK*NH];
__device__ float g_y[TOK*DI];
__device__ float g_feat[BATCH*FEATD];
__device__ __nv_bfloat16 g_wihi[NL*DIP*DM];
__device__ __nv_bfloat16 g_wilo[NL*DIP*DM];
__device__ __nv_bfloat16 g_wohi[NL*DM*DI];
__device__ __nv_bfloat16 g_wolo[NL*DM*DI];
__device__ __nv_bfloat16 g_ahi[TOK*DI];
__device__ __nv_bfloat16 g_alo[TOK*DI];

// ================= helpers =================
typedef unsigned long long u64t;
__device__ __forceinline__ uint32_t smem_u32(const void* p) {
    uint32_t a;
    asm("{ .reg .u64 t; cvta.to.shared.u64 t, %1; cvt.u32.u64 %0, t; }" : "=r"(a) : "l"(p));
    return a;
}
__device__ __forceinline__ void ldm4(uint32_t* r, uint32_t addr) {
    asm volatile("ldmatrix.sync.aligned.m8n8.x4.shared.b16 {%0,%1,%2,%3}, [%4];"
                 : "=r"(r[0]), "=r"(r[1]), "=r"(r[2]), "=r"(r[3]) : "r"(addr));
}
__device__ __forceinline__ void mma16816(float* c, const uint32_t* a, uint32_t b0, uint32_t b1) {
    asm volatile("mma.sync.aligned.m16n8k16.row.col.f32.bf16.bf16.f32 "
                 "{%0,%1,%2,%3}, {%4,%5,%6,%7}, {%8,%9}, {%0,%1,%2,%3};"
                 : "+f"(c[0]), "+f"(c[1]), "+f"(c[2]), "+f"(c[3])
                 : "r"(a[0]), "r"(a[1]), "r"(a[2]), "r"(a[3]), "r"(b0), "r"(b1));
}
__device__ __forceinline__ void cp16(uint32_t dst, const void* src, int sz) {
    asm volatile("cp.async.cg.shared.global [%0], [%1], 16, %2;"
                 :: "r"(dst), "l"(src), "r"(sz) : "memory");
}
__device__ __forceinline__ void cp4(uint32_t dst, const void* src) {
    asm volatile("cp.async.ca.shared.global [%0], [%1], 4;"
                 :: "r"(dst), "l"(src) : "memory");
}
#define CP_COMMIT() asm volatile("cp.async.commit_group;" ::: "memory")
#define CP_WAIT3()  asm volatile("cp.async.wait_group 3;" ::: "memory")
#define CP_WAIT1()  asm volatile("cp.async.wait_group 1;" ::: "memory")
#define CP_WAIT0()  asm volatile("cp.async.wait_group 0;" ::: "memory")

// f32x2 packed ops (base sm_100 family; non-'a' feature)
__device__ __forceinline__ u64t pk2(float lo, float hi) {
    u64t r; asm("mov.b64 %0, {%1, %2};" : "=l"(r) : "f"(lo), "f"(hi)); return r;
}
__device__ __forceinline__ void upk2(u64t v, float& lo, float& hi) {
    asm("mov.b64 {%0, %1}, %2;" : "=f"(lo), "=f"(hi) : "l"(v));
}
__device__ __forceinline__ u64t mul2_(u64t a, u64t b) {
    u64t d; asm("mul.rn.f32x2 %0, %1, %2;" : "=l"(d) : "l"(a), "l"(b)); return d;
}
__device__ __forceinline__ u64t fma2_(u64t a, u64t b, u64t c) {
    u64t d; asm("fma.rn.f32x2 %0, %1, %2, %3;" : "=l"(d) : "l"(a), "l"(b), "l"(c)); return d;
}

__device__ __forceinline__ void split2(float x, float y, uint32_t& h, uint32_t& l) {
    __nv_bfloat162 hh = __floats2bfloat162_rn(x, y);
    float2 f = __bfloat1622float2(hh);
    __nv_bfloat162 ll = __floats2bfloat162_rn(x - f.x, y - f.y);
    h = *(uint32_t*)&hh; l = *(uint32_t*)&ll;
}

// ---------------- fused weight split ----------------
#define NIN4 ((long)NL*DIP*DM/4)
#define NOUT4 ((long)NL*DM*DI/4)
__global__ void k_split_all(const float4* __restrict__ wi, const float4* __restrict__ wo,
                            uint2* __restrict__ wihi, uint2* __restrict__ wilo,
                            uint2* __restrict__ wohi, uint2* __restrict__ wolo) {
    long i = (long)blockIdx.x * blockDim.x + threadIdx.x;
    const float4* src; uint2 *hi, *lo; long idx;
    if (i < NIN4) { src = wi; hi = wihi; lo = wilo; idx = i; }
    else if (i < NIN4 + NOUT4) { src = wo; hi = wohi; lo = wolo; idx = i - NIN4; }
    else return;
    float4 v = src[idx];
    uint2 h, l;
    split2(v.x, v.y, h.x, l.x);
    split2(v.z, v.w, h.y, l.y);
    hi[idx] = h; lo[idx] = l;
}

// ============ split-bf16 HMMA GEMM (R7 winner config) ============
#define SA_HI 0
#define SA_LO (128*64)
#define SB_HI (2*128*64)
#define SB_LO (2*128*64 + 64*64)
#define STAGE (2*128*64 + 2*64*64)     // 24576 B
#define GEMM_SMEM (2*STAGE)            // 49152 B

__global__ void __launch_bounds__(128, 4) k_gemm_mma(
        const __nv_bfloat16* __restrict__ Ahi, const __nv_bfloat16* __restrict__ Alo,
        const __nv_bfloat16* __restrict__ Bhi, const __nv_bfloat16* __restrict__ Blo,
        float* __restrict__ C, int N, int K, int beta) {
    extern __shared__ __align__(16) char smem[];
    int tid = threadIdx.x;
    int wid = tid >> 5, lane = tid & 31;
    int m0 = blockIdx.x * 128;
    int n0 = blockIdx.y * 64;
    int wm = wid & 1;
    int wn = wid >> 1;
    uint32_t sb = smem_u32(smem);

    float acc[4][4][4];
#pragma unroll
    for (int i = 0; i < 4; i++)
#pragma unroll
        for (int j = 0; j < 4; j++)
#pragma unroll
            for (int q = 0; q < 4; q++) acc[i][j][q] = 0.f;

    int rbA = wm*64 + (lane & 15);
    int lcA = lane >> 4;
    int swA = (rbA >> 1) & 3;
    int rbB = wn*32 + (lane & 7) + ((lane >> 4) & 1) * 8;
    int lcB = (lane >> 3) & 1;
    int swB = (rbB >> 1) & 3;

    const int NK = K >> 5;

    auto issue = [&](int kc) {
        uint32_t stg = sb + (uint32_t)(kc & 1) * STAGE;
        size_t kbyte = (size_t)(kc << 5) * 2;
#pragma unroll
        for (int j = 0; j < 4; j++) {
            int idx = (j << 7) + tid;
            int r = idx >> 2, c = idx & 3;
            int cs = c ^ ((r >> 1) & 3);
            size_t arow = ((size_t)(m0 + r) * K) * 2 + kbyte + c*16;
            cp16(stg + SA_HI + r*64 + cs*16, (const char*)Ahi + arow, 16);
            cp16(stg + SA_LO + r*64 + cs*16, (const char*)Alo + arow, 16);
        }
#pragma unroll
        for (int j = 0; j < 2; j++) {
            int idx = (j << 7) + tid;
            int r = idx >> 2, c = idx & 3;
            int cs = c ^ ((r >> 1) & 3);
            int bn = n0 + r;
            int ok = (bn < N) ? 16 : 0;
            int bnc = (bn < N) ? bn : (N - 1);
            size_t brow = ((size_t)bnc * K) * 2 + kbyte + c*16;
            cp16(stg + SB_HI + r*64 + cs*16, (const char*)Bhi + brow, ok);
            cp16(stg + SB_LO + r*64 + cs*16, (const char*)Blo + brow, ok);
        }
        CP_COMMIT();
    };

    issue(0);

    for (int kc = 0; kc < NK; kc++) {
        if (kc + 1 < NK) { issue(kc + 1); CP_WAIT1(); }
        else            { CP_WAIT0(); }
        __syncthreads();
        uint32_t stg = sb + (uint32_t)(kc & 1) * STAGE;
#pragma unroll
        for (int kk = 0; kk < 2; kk++) {
            uint32_t czA = (uint32_t)((((kk << 1) | lcA) ^ swA) * 16);
            uint32_t czB = (uint32_t)((((kk << 1) | lcB) ^ swB) * 16);
            uint32_t adrAhi = stg + SA_HI + (uint32_t)rbA*64 + czA;
            uint32_t adrAlo = stg + SA_LO + (uint32_t)rbA*64 + czA;
            uint32_t adrBhi = stg + SB_HI + (uint32_t)rbB*64 + czB;
            uint32_t adrBlo = stg + SB_LO + (uint32_t)rbB*64 + czB;
            uint32_t fa[4][4], fb[2][4], fbl[2][4];
#pragma unroll
            for (int mt = 0; mt < 4; mt++) ldm4(fa[mt], adrAhi + mt*16*64);
#pragma unroll
            for (int bt = 0; bt < 2; bt++) ldm4(fb[bt], adrBhi + bt*16*64);
#pragma unroll
            for (int mt = 0; mt < 4; mt++)
#pragma unroll
                for (int nt = 0; nt < 4; nt++)
                    mma16816(acc[mt][nt], fa[mt], fb[nt>>1][(nt&1)*2], fb[nt>>1][(nt&1)*2+1]);
#pragma unroll
            for (int bt = 0; bt < 2; bt++) ldm4(fbl[bt], adrBlo + bt*16*64);
#pragma unroll
            for (int mt = 0; mt < 4; mt++)
#pragma unroll
                for (int nt = 0; nt < 4; nt++)
                    mma16816(acc[mt][nt], fa[mt], fbl[nt>>1][(nt&1)*2], fbl[nt>>1][(nt&1)*2+1]);
#pragma unroll
            for (int mt = 0; mt < 4; mt++) ldm4(fa[mt], adrAlo + mt*16*64);
#pragma unroll
            for (int mt = 0; mt < 4; mt++)
#pragma unroll
                for (int nt = 0; nt < 4; nt++)
                    mma16816(acc[mt][nt], fa[mt], fb[nt>>1][(nt&1)*2], fb[nt>>1][(nt&1)*2+1]);
        }
        __syncthreads();
    }

    int mbase = m0 + wm*64 + (lane >> 2);
    int nbase = n0 + wn*32 + (lane & 3)*2;
#pragma unroll
    for (int mt = 0; mt < 4; mt++) {
#pragma unroll
        for (int nt = 0; nt < 4; nt++) {
            int n = nbase + nt*8;
            if (n < N) {
                int m = mbase + mt*16;
                float2 v0 = make_float2(acc[mt][nt][0], acc[mt][nt][1]);
                float2 v1 = make_float2(acc[mt][nt][2], acc[mt][nt][3]);
                float* p0 = &C[(size_t)m * N + n];
                float* p1 = &C[(size_t)(m + 8) * N + n];
                if (beta) {
                    float2 o0 = *(float2*)p0, o1 = *(float2*)p1;
                    v0.x += o0.x; v0.y += o0.y; v1.x += o1.x; v1.y += o1.y;
                }
                *(float2*)p0 = v0;
                *(float2*)p1 = v1;
            }
        }
    }
}

// ---------------- embedding gather (float4) ----------------
__global__ void k_embed(const int* __restrict__ ids, const float* __restrict__ emb,
                        float* __restrict__ h) {
    int i = blockIdx.x * blockDim.x + threadIdx.x;
    if (i >= TOK*DM/4) return;
    int t = i / (DM/4), d4 = i % (DM/4);
    ((float4*)h)[i] = ((const float4*)emb)[(long)ids[t]*(DM/4) + d4];
}

// ---------------- rmsnorm -> bf16 hi/lo (float4) ----------------
__global__ void k_rmsnorm_split(const float* __restrict__ in, const float* __restrict__ w,
                                __nv_bfloat16* __restrict__ ohi, __nv_bfloat16* __restrict__ olo,
                                int D) {
    int row = blockIdx.x;
    const float4* x4 = (const float4*)(in + (long)row*D);
    int nd4 = D >> 2;
    float ss = 0.f;
    for (int d = threadIdx.x; d < nd4; d += blockDim.x) {
        float4 v = x4[d];
        ss += v.x*v.x + v.y*v.y + v.z*v.z + v.w*v.w;
    }
    __shared__ float red[32];
    for (int o = 16; o; o >>= 1) ss += __shfl_down_sync(0xffffffffu, ss, o);
    if ((threadIdx.x & 31) == 0) red[threadIdx.x >> 5] = ss;
    __syncthreads();
    if (threadIdx.x < 32) {
        float v = (threadIdx.x < (blockDim.x >> 5)) ? red[threadIdx.x] : 0.f;
        for (int o = 16; o; o >>= 1) v += __shfl_down_sync(0xffffffffu, v, o);
        if (threadIdx.x == 0) red[0] = rsqrtf(v / (float)D + EPSV);
    }
    __syncthreads();
    float s = red[0];
    const float4* w4 = (const float4*)w;
    uint2* h2 = (uint2*)(ohi + (long)row*D);
    uint2* l2 = (uint2*)(olo + (long)row*D);
    for (int d = threadIdx.x; d < nd4; d += blockDim.x) {
        float4 v = x4[d], ww = w4[d];
        v.x *= s*ww.x; v.y *= s*ww.y; v.z *= s*ww.z; v.w *= s*ww.w;
        uint2 h, l;
        split2(v.x, v.y, h.x, l.x);
        split2(v.z, v.w, h.y, l.y);
        h2[d] = h; l2[d] = l;
    }
}

// ---------------- plain rmsnorm (final, float4) ----------------
__global__ void k_rmsnorm(const float* __restrict__ in, const float* __restrict__ w,
                          float* __restrict__ out, int D) {
    int row = blockIdx.x;
    const float4* x4 = (const float4*)(in + (long)row*D);
    int nd4 = D >> 2;
    float ss = 0.f;
    for (int d = threadIdx.x; d < nd4; d += blockDim.x) {
        float4 v = x4[d];
        ss += v.x*v.x + v.y*v.y + v.z*v.z + v.w*v.w;
    }
    __shared__ float red[32];
    for (int o = 16; o; o >>= 1) ss += __shfl_down_sync(0xffffffffu, ss, o);
    if ((threadIdx.x & 31) == 0) red[threadIdx.x >> 5] = ss;
    __syncthreads();
    if (threadIdx.x < 32) {
        float v = (threadIdx.x < (blockDim.x >> 5)) ? red[threadIdx.x] : 0.f;
        for (int o = 16; o; o >>= 1) v += __shfl_down_sync(0xffffffffu, v, o);
        if (threadIdx.x == 0) red[0] = rsqrtf(v / (float)D + EPSV);
    }
    __syncthreads();
    float s = red[0];
    const float4* w4 = (const float4*)w;
    float4* o4 = (float4*)(out + (long)row*D);
    for (int d = threadIdx.x; d < nd4; d += blockDim.x) {
        float4 v = x4[d], ww = w4[d];
        v.x *= s*ww.x; v.y *= s*ww.y; v.z *= s*ww.z; v.w *= s*ww.w;
        o4[d] = v;
    }
}

// ---------------- fused conv+silu and dt=softplus (R9 scalar form) ----------------
__global__ void k_convdt(const float* __restrict__ zx, const float* __restrict__ w,
                         const float* __restrict__ bconv, const float* __restrict__ dtb,
                         float* __restrict__ xBC, float* __restrict__ dtout) {
    int i = blockIdx.x * blockDim.x + threadIdx.x;
    if (i < TOK*CONVD) {
        int c = i % CONVD;
        int t = i / CONVD;
        int s = t % SEQL;
        const float* src = zx + (long)t*DIP + DI + c;
        float acc = bconv[c];
#pragma unroll
        for (int k = 0; k < KC; k++) {
            int ss = s - (KC-1) + k;
            if (ss >= 0) acc += w[c*KC + k] * src[(long)(ss - s) * DIP];
        }
        xBC[i] = acc / (1.f + expf(-acc));
    } else {
        int j = i - TOK*CONVD;
        if (j >= TOK*NH) return;
        int h = j % NH, t = j / NH;
        float v = zx[(long)t*DIP + DI + CONVD + h] + dtb[h];
        dtout[j] = (v > 20.f) ? v : log1pf(expf(v));
    }
}

// ---------------- SSD scan: R9 layout + f32x2 packed FMA ----------------
#define SC_STGF 656
#define SC_STGB (SC_STGF*4)
__global__ void __launch_bounds__(256, 2) k_scan(
        const float* __restrict__ xBC, const float* __restrict__ dt,
        const float* __restrict__ A_log, const float* __restrict__ Dvec,
        float* __restrict__ y) {
    int b = blockIdx.x / NH;
    int h = blockIdx.x % NH;
    float A = -expf(A_log[h]);
    float Dh = Dvec[h];
    int tid = threadIdx.x;
    int pi = tid >> 4;
    int ni = tid & 15;

    __shared__ __align__(16) float ring[4*SC_STGF];
    uint32_t rb = smem_u32(ring);
    const float* base = xBC + (long)b*SEQL*CONVD;
    const float* dbase = dt + ((long)b*SEQL)*NH + h;

    u64t st2[4][4];
#pragma unroll
    for (int i = 0; i < 4; i++)
#pragma unroll
        for (int j = 0; j < 4; j++) st2[i][j] = 0ULL;

    auto issue = [&](int s) {
        uint32_t sa = rb + (uint32_t)(s & 3) * SC_STGB;
        const float* r0 = base + (long)(2*s) * CONVD;
        const float* r1 = r0 + CONVD;
        if (tid < 32)        cp16(sa +            tid*16,       r0 + DI + tid*4, 16);
        else if (tid < 64)   cp16(sa + 512  + (tid-32)*16,      r0 + DI + DS + (tid-32)*4, 16);
        else if (tid < 96)   cp16(sa + 1024 + (tid-64)*16,      r1 + DI + (tid-64)*4, 16);
        else if (tid < 128)  cp16(sa + 1536 + (tid-96)*16,      r1 + DI + DS + (tid-96)*4, 16);
        else if (tid < 144)  cp16(sa + 2048 + (tid-128)*16,     r0 + h*HD + (tid-128)*4, 16);
        else if (tid < 160)  cp16(sa + 2304 + (tid-144)*16,     r1 + h*HD + (tid-144)*4, 16);
        else if (tid == 160) cp4(sa + 2560, dbase + (long)(2*s)*NH);
        else if (tid == 161) cp4(sa + 2564, dbase + (long)(2*s+1)*NH);
        CP_COMMIT();
    };

    issue(0); issue(1); issue(2); issue(3);

    const int NPAIR = SEQL/2;
    for (int s = 0; s < NPAIR; s++) {
        CP_WAIT3();
        __syncthreads();
        const float* stg = ring + (s & 3) * SC_STGF;
#pragma unroll
        for (int half = 0; half < 2; half++) {
            int t = 2*s + half;
            float dtt = stg[640 + half];
            float decay = expf(dtt * A);
            u64t decay2 = pk2(decay, decay);
            u64t dt2 = pk2(dtt, dtt);
            const float* Bp = stg + half*256;
            const float* Cp = Bp + 128;
            u64t B2[4], C2[4];
            {
                ulonglong2 bb0 = *(const ulonglong2*)&Bp[ni*8];
                ulonglong2 bb1 = *(const ulonglong2*)&Bp[ni*8 + 4];
                B2[0] = bb0.x; B2[1] = bb0.y; B2[2] = bb1.x; B2[3] = bb1.y;
                ulonglong2 cc0 = *(const ulonglong2*)&Cp[ni*8];
                ulonglong2 cc1 = *(const ulonglong2*)&Cp[ni*8 + 4];
                C2[0] = cc0.x; C2[1] = cc0.y; C2[2] = cc1.x; C2[3] = cc1.y;
            }
            u64t dtB2[4];
#pragma unroll
            for (int j = 0; j < 4; j++) dtB2[j] = mul2_(dt2, B2[j]);
            const float* xp = stg + 512 + half*64;
            float vout[4];
#pragma unroll
            for (int pp = 0; pp < 4; pp++) {
                float xv = xp[pi*4 + pp];
                u64t x2 = pk2(xv, xv);
                u64t acc2 = 0ULL;
#pragma unroll
                for (int j = 0; j < 4; j++) {
                    st2[pp][j] = fma2_(st2[pp][j], decay2, mul2_(x2, dtB2[j]));
                    acc2 = fma2_(st2[pp][j], C2[j], acc2);
                }
                float a0, a1;
                upk2(acc2, a0, a1);
                float a = a0 + a1;
                a += __shfl_down_sync(0xffffffffu, a, 8, 16);
                a += __shfl_down_sync(0xffffffffu, a, 4, 16);
                a += __shfl_down_sync(0xffffffffu, a, 2, 16);
                a += __shfl_down_sync(0xffffffffu, a, 1, 16);
                vout[pp] = a + Dh * xv;
            }
            if (ni == 0) {
                float4 v = make_float4(vout[0], vout[1], vout[2], vout[3]);
                *(float4*)&y[((long)b*SEQL + t)*DI + h*HD + pi*4] = v;
            }
        }
        __syncthreads();
        if (s + 4 < NPAIR) issue(s + 4);
        else CP_COMMIT();
    }
}

// ---------------- y = rmsnorm(y * silu(z)) * w -> bf16 hi/lo (float4) ----------------
__global__ void k_gatenorm_split(const float* __restrict__ yin, const float* __restrict__ zx,
                                 const float* __restrict__ w,
                                 __nv_bfloat16* __restrict__ ohi, __nv_bfloat16* __restrict__ olo) {
    int row = blockIdx.x;
    const float4* yr = (const float4*)(yin + (long)row*DI);
    const float4* zr = (const float4*)(zx + (long)row*DIP);
    __shared__ __align__(16) float sv[DI];
    float ss = 0.f;
    const int nd4 = DI >> 2;
    for (int d = threadIdx.x; d < nd4; d += blockDim.x) {
        float4 zv = zr[d], yv = yr[d];
        float4 v;
        v.x = yv.x * (zv.x / (1.f + expf(-zv.x)));
        v.y = yv.y * (zv.y / (1.f + expf(-zv.y)));
        v.z = yv.z * (zv.z / (1.f + expf(-zv.z)));
        v.w = yv.w * (zv.w / (1.f + expf(-zv.w)));
        ((float4*)sv)[d] = v;
        ss += v.x*v.x + v.y*v.y + v.z*v.z + v.w*v.w;
    }
    __shared__ float red[32];
    for (int o = 16; o; o >>= 1) ss += __shfl_down_sync(0xffffffffu, ss, o);
    if ((threadIdx.x & 31) == 0) red[threadIdx.x >> 5] = ss;
    __syncthreads();
    if (threadIdx.x < 32) {
        float v = (threadIdx.x < (blockDim.x >> 5)) ? red[threadIdx.x] : 0.f;
        for (int o = 16; o; o >>= 1) v += __shfl_down_sync(0xffffffffu, v, o);
        if (threadIdx.x == 0) red[0] = rsqrtf(v / (float)DI + EPSV);
    }
    __syncthreads();
    float s = red[0];
    const float4* w4 = (const float4*)w;
    uint2* h2 = (uint2*)(ohi + (long)row*DI);
    uint2* l2 = (uint2*)(olo + (long)row*DI);
    for (int d = threadIdx.x; d < nd4; d += blockDim.x) {
        float4 v = ((float4*)sv)[d], ww = w4[d];
        v.x *= s*ww.x; v.y *= s*ww.y; v.z *= s*ww.z; v.w *= s*ww.w;
        uint2 h, l;
        split2(v.x, v.y, h.x, l.x);
        split2(v.z, v.w, h.y, l.y);
        h2[d] = h; l2[d] = l;
    }
}

// ---------------- masked mean pool + cat embed concat ----------------
__global__ void k_pool(const float* __restrict__ x, const int* __restrict__ mask,
                       const int* __restrict__ cats, const float* __restrict__ cat_emb,
                       float* __restrict__ feat) {
    int b = blockIdx.x;
    __shared__ float sm[SEQL];
    __shared__ float minv;
    for (int t = threadIdx.x; t < SEQL; t += blockDim.x)
        sm[t] = (float)mask[b*SEQL + t];
    __syncthreads();
    if (threadIdx.x == 0) {
        float s = 0.f;
        for (int t = 0; t < SEQL; t++) s += sm[t];
        if (s < 1e-9f) s = 1e-9f;
        minv = 1.f / s;
    }
    __syncthreads();
    for (int d = threadIdx.x; d < DM; d += blockDim.x) {
        float acc = 0.f;
        for (int t = 0; t < SEQL; t++)
            acc += sm[t] * x[((long)b*SEQL + t)*DM + d];
        feat[b*FEATD + d] = acc * minv;
    }
    if (threadIdx.x < 16)
        feat[b*FEATD + DM + threadIdx.x] = cat_emb[cats[b]*16 + threadIdx.x];
}

// ---------------- classifier heads ----------------
__global__ void k_heads(const float* __restrict__ feat,
                        const float* __restrict__ qw, const float* __restrict__ qb,
                        const float* __restrict__ aw, const float* __restrict__ ab,
                        float* __restrict__ out) {
    int b = blockIdx.y, j = blockIdx.x;
    const float* w;
    float bias;
    if (j < 21) { w = qw + j*FEATD; bias = qb[j]; }
    else        { w = aw + (j-21)*FEATD; bias = ab[j-21]; }
    float s = 0.f;
    for (int d = threadIdx.x; d < FEATD; d += blockDim.x)
        s += feat[b*FEATD + d] * w[d];
    __shared__ float red[8];
    for (int o = 16; o; o >>= 1) s += __shfl_down_sync(0xffffffffu, s, o);
    if ((threadIdx.x & 31) == 0) red[threadIdx.x >> 5] = s;
    __syncthreads();
    if (threadIdx.x == 0) {
        float v = 0.f;
        for (int i = 0; i < (int)(blockDim.x >> 5); i++) v += red[i];
        out[b*30 + j] = v + bias;
    }
}

// ---------------- host orchestration ----------------
extern "C" void kernel_launch(void* const* d_in, const int* in_sizes, int n_in,
                              void* d_out, int out_size) {
    const int*   ids      = (const int*)d_in[0];
    const int*   mask     = (const int*)d_in[1];
    const int*   cats     = (const int*)d_in[2];
    const float* emb      = (const float*)d_in[3];
    const float* norm_w   = (const float*)d_in[4];
    const float* in_proj  = (const float*)d_in[5];
    const float* conv_w   = (const float*)d_in[6];
    const float* conv_b   = (const float*)d_in[7];
    const float* dt_bias  = (const float*)d_in[8];
    const float* A_log    = (const float*)d_in[9];
    const float* Dvec     = (const float*)d_in[10];
    const float* gnorm_w  = (const float*)d_in[11];
    const float* out_proj = (const float*)d_in[12];
    const float* final_w  = (const float*)d_in[13];
    const float* cat_emb  = (const float*)d_in[14];
    const float* qw       = (const float*)d_in[15];
    const float* qb       = (const float*)d_in[16];
    const float* aw       = (const float*)d_in[17];
    const float* ab       = (const float*)d_in[18];
    float* out = (float*)d_out;

    float *p_h, *p_x, *p_zx, *p_xBC, *p_dt, *p_y, *p_feat;
    __nv_bfloat16 *p_wihi, *p_wilo, *p_wohi, *p_wolo, *p_ahi, *p_alo;
    cudaGetSymbolAddress((void**)&p_h,    g_h);
    cudaGetSymbolAddress((void**)&p_x,    g_x);
    cudaGetSymbolAddress((void**)&p_zx,   g_zx);
    cudaGetSymbolAddress((void**)&p_xBC,  g_xBC);
    cudaGetSymbolAddress((void**)&p_dt,   g_dt);
    cudaGetSymbolAddress((void**)&p_y,    g_y);
    cudaGetSymbolAddress((void**)&p_feat, g_feat);
    cudaGetSymbolAddress((void**)&p_wihi, g_wihi);
    cudaGetSymbolAddress((void**)&p_wilo, g_wilo);
    cudaGetSymbolAddress((void**)&p_wohi, g_wohi);
    cudaGetSymbolAddress((void**)&p_wolo, g_wolo);
    cudaGetSymbolAddress((void**)&p_ahi,  g_ahi);
    cudaGetSymbolAddress((void**)&p_alo,  g_alo);

    cudaFuncSetAttribute(k_gemm_mma, cudaFuncAttributeMaxDynamicSharedMemorySize, GEMM_SMEM);

    {
        long ntot = NIN4 + NOUT4;
        k_split_all<<<(unsigned)((ntot + 255)/256), 256>>>(
            (const float4*)in_proj, (const float4*)out_proj,
            (uint2*)p_wihi, (uint2*)p_wilo, (uint2*)p_wohi, (uint2*)p_wolo);
    }
    {
        int n = TOK*DM/4;
        k_embed<<<(n + 255)/256, 256>>>(ids, emb, p_h);
    }

    for (int l = 0; l < NL; l++) {
        k_rmsnorm_split<<<TOK, 256>>>(p_h, norm_w + l*DM, p_ahi, p_alo, DM);
        {
            dim3 grid(TOK/128, (DIP + 63)/64);
            k_gemm_mma<<<grid, 128, GEMM_SMEM>>>(p_ahi, p_alo,
                                                 p_wihi + (long)l*DIP*DM, p_wilo + (long)l*DIP*DM,
                                                 p_zx, DIP, DM, 0);
        }
        {
            int n = TOK*CONVD + TOK*NH;
            k_convdt<<<(n + 255)/256, 256>>>(p_zx, conv_w + (long)l*CONVD*KC,
                                             conv_b + l*CONVD, dt_bias + l*NH,
                                             p_xBC, p_dt);
        }
        k_scan<<<BATCH*NH, 256>>>(p_xBC, p_dt, A_log + l*NH, Dvec + l*NH, p_y);
        k_gatenorm_split<<<TOK, 256>>>(p_y, p_zx, gnorm_w + (long)l*DI, p_ahi, p_alo);
        {
            dim3 grid(TOK/128, DM/64);
            k_gemm_mma<<<grid, 128, GEMM_SMEM>>>(p_ahi, p_alo,
                                                 p_wohi + (long)l*DM*DI, p_wolo + (long)l*DM*DI,
                                                 p_h, DM, DI, 1);
        }
    }

    k_rmsnorm<<<TOK, 256>>>(p_h, final_w, p_x, DM);
    k_pool<<<BATCH, 256>>>(p_x, mask, cats, cat_emb, p_feat);
    {
        dim3 grid(30, BATCH);
        k_heads<<<grid, 128>>>(p_feat, qw, qb, aw, ab, out);
    }
}

// round 12
// speedup vs baseline: 1.1928x; 1.0674x over previous
#include <cuda_runtime.h>
#include <cuda_bf16.h>
#include <cstdint>

#define BATCH 4
#define SEQL 512
#define TOK (BATCH*SEQL)
#define DM 1536
#define DIP 6448
#define DI 3072
#define CONVD 3328
#define NH 48
#define HD 64
#define DS 128
#define NL 4
#define KC 4
#define FEATD 1552
#define EPSV 1e-5f

// ---------------- workspace ----------------
__device__ float g_h[TOK*DM];
__device__ float g_x[TOK*DM];
__device__ float g_zx[TOK*DIP];
__device__ float g_xBC[TOK*CONVD];
__device__ float g_dt[TOK*NH];
__device__ float g_y[TOK*DI];
__device__ float g_feat[BATCH*FEATD];
__device__ __nv_bfloat16 g_wihi[NL*DIP*DM];
__device__ __nv_bfloat16 g_wilo[NL*DIP*DM];
__device__ __nv_bfloat16 g_wohi[NL*DM*DI];
__device__ __nv_bfloat16 g_wolo[NL*DM*DI];
__device__ __nv_bfloat16 g_ahi[TOK*DI];
__device__ __nv_bfloat16 g_alo[TOK*DI];

// ================= helpers =================
typedef unsigned long long u64t;
__device__ __forceinline__ uint32_t smem_u32(const void* p) {
    uint32_t a;
    asm("{ .reg .u64 t; cvta.to.shared.u64 t, %1; cvt.u32.u64 %0, t; }" : "=r"(a) : "l"(p));
    return a;
}
__device__ __forceinline__ void ldm4(uint32_t* r, uint32_t addr) {
    asm volatile("ldmatrix.sync.aligned.m8n8.x4.shared.b16 {%0,%1,%2,%3}, [%4];"
                 : "=r"(r[0]), "=r"(r[1]), "=r"(r[2]), "=r"(r[3]) : "r"(addr));
}
__device__ __forceinline__ void mma16816(float* c, const uint32_t* a, uint32_t b0, uint32_t b1) {
    asm volatile("mma.sync.aligned.m16n8k16.row.col.f32.bf16.bf16.f32 "
                 "{%0,%1,%2,%3}, {%4,%5,%6,%7}, {%8,%9}, {%0,%1,%2,%3};"
                 : "+f"(c[0]), "+f"(c[1]), "+f"(c[2]), "+f"(c[3])
                 : "r"(a[0]), "r"(a[1]), "r"(a[2]), "r"(a[3]), "r"(b0), "r"(b1));
}
__device__ __forceinline__ void cp16(uint32_t dst, const void* src, int sz) {
    asm volatile("cp.async.cg.shared.global [%0], [%1], 16, %2;"
                 :: "r"(dst), "l"(src), "r"(sz) : "memory");
}
__device__ __forceinline__ void cp4(uint32_t dst, const void* src) {
    asm volatile("cp.async.ca.shared.global [%0], [%1], 4;"
                 :: "r"(dst), "l"(src) : "memory");
}
#define CP_COMMIT() asm volatile("cp.async.commit_group;" ::: "memory")
#define CP_WAIT3()  asm volatile("cp.async.wait_group 3;" ::: "memory")
#define CP_WAIT1()  asm volatile("cp.async.wait_group 1;" ::: "memory")
#define CP_WAIT0()  asm volatile("cp.async.wait_group 0;" ::: "memory")

// f32x2 packed ops
__device__ __forceinline__ u64t pk2(float lo, float hi) {
    u64t r; asm("mov.b64 %0, {%1, %2};" : "=l"(r) : "f"(lo), "f"(hi)); return r;
}
__device__ __forceinline__ void upk2(u64t v, float& lo, float& hi) {
    asm("mov.b64 {%0, %1}, %2;" : "=f"(lo), "=f"(hi) : "l"(v));
}
__device__ __forceinline__ u64t mul2_(u64t a, u64t b) {
    u64t d; asm("mul.rn.f32x2 %0, %1, %2;" : "=l"(d) : "l"(a), "l"(b)); return d;
}
__device__ __forceinline__ u64t fma2_(u64t a, u64t b, u64t c) {
    u64t d; asm("fma.rn.f32x2 %0, %1, %2, %3;" : "=l"(d) : "l"(a), "l"(b), "l"(c)); return d;
}

__device__ __forceinline__ void split2(float x, float y, uint32_t& h, uint32_t& l) {
    __nv_bfloat162 hh = __floats2bfloat162_rn(x, y);
    float2 f = __bfloat1622float2(hh);
    __nv_bfloat162 ll = __floats2bfloat162_rn(x - f.x, y - f.y);
    h = *(uint32_t*)&hh; l = *(uint32_t*)&ll;
}

// ---------------- fused weight split ----------------
#define NIN4 ((long)NL*DIP*DM/4)
#define NOUT4 ((long)NL*DM*DI/4)
__global__ void k_split_all(const float4* __restrict__ wi, const float4* __restrict__ wo,
                            uint2* __restrict__ wihi, uint2* __restrict__ wilo,
                            uint2* __restrict__ wohi, uint2* __restrict__ wolo) {
    long i = (long)blockIdx.x * blockDim.x + threadIdx.x;
    const float4* src; uint2 *hi, *lo; long idx;
    if (i < NIN4) { src = wi; hi = wihi; lo = wilo; idx = i; }
    else if (i < NIN4 + NOUT4) { src = wo; hi = wohi; lo = wolo; idx = i - NIN4; }
    else return;
    float4 v = src[idx];
    uint2 h, l;
    split2(v.x, v.y, h.x, l.x);
    split2(v.z, v.w, h.y, l.y);
    hi[idx] = h; lo[idx] = l;
}

// ============ split-bf16 HMMA GEMM (R7 winner config) ============
#define SA_HI 0
#define SA_LO (128*64)
#define SB_HI (2*128*64)
#define SB_LO (2*128*64 + 64*64)
#define STAGE (2*128*64 + 2*64*64)
#define GEMM_SMEM (2*STAGE)

__global__ void __launch_bounds__(128, 4) k_gemm_mma(
        const __nv_bfloat16* __restrict__ Ahi, const __nv_bfloat16* __restrict__ Alo,
        const __nv_bfloat16* __restrict__ Bhi, const __nv_bfloat16* __restrict__ Blo,
        float* __restrict__ C, int N, int K, int beta) {
    extern __shared__ __align__(16) char smem[];
    int tid = threadIdx.x;
    int wid = tid >> 5, lane = tid & 31;
    int m0 = blockIdx.x * 128;
    int n0 = blockIdx.y * 64;
    int wm = wid & 1;
    int wn = wid >> 1;
    uint32_t sb = smem_u32(smem);

    float acc[4][4][4];
#pragma unroll
    for (int i = 0; i < 4; i++)
#pragma unroll
        for (int j = 0; j < 4; j++)
#pragma unroll
            for (int q = 0; q < 4; q++) acc[i][j][q] = 0.f;

    int rbA = wm*64 + (lane & 15);
    int lcA = lane >> 4;
    int swA = (rbA >> 1) & 3;
    int rbB = wn*32 + (lane & 7) + ((lane >> 4) & 1) * 8;
    int lcB = (lane >> 3) & 1;
    int swB = (rbB >> 1) & 3;

    const int NK = K >> 5;

    auto issue = [&](int kc) {
        uint32_t stg = sb + (uint32_t)(kc & 1) * STAGE;
        size_t kbyte = (size_t)(kc << 5) * 2;
#pragma unroll
        for (int j = 0; j < 4; j++) {
            int idx = (j << 7) + tid;
            int r = idx >> 2, c = idx & 3;
            int cs = c ^ ((r >> 1) & 3);
            size_t arow = ((size_t)(m0 + r) * K) * 2 + kbyte + c*16;
            cp16(stg + SA_HI + r*64 + cs*16, (const char*)Ahi + arow, 16);
            cp16(stg + SA_LO + r*64 + cs*16, (const char*)Alo + arow, 16);
        }
#pragma unroll
        for (int j = 0; j < 2; j++) {
            int idx = (j << 7) + tid;
            int r = idx >> 2, c = idx & 3;
            int cs = c ^ ((r >> 1) & 3);
            int bn = n0 + r;
            int ok = (bn < N) ? 16 : 0;
            int bnc = (bn < N) ? bn : (N - 1);
            size_t brow = ((size_t)bnc * K) * 2 + kbyte + c*16;
            cp16(stg + SB_HI + r*64 + cs*16, (const char*)Bhi + brow, ok);
            cp16(stg + SB_LO + r*64 + cs*16, (const char*)Blo + brow, ok);
        }
        CP_COMMIT();
    };

    issue(0);

    for (int kc = 0; kc < NK; kc++) {
        if (kc + 1 < NK) { issue(kc + 1); CP_WAIT1(); }
        else            { CP_WAIT0(); }
        __syncthreads();
        uint32_t stg = sb + (uint32_t)(kc & 1) * STAGE;
#pragma unroll
        for (int kk = 0; kk < 2; kk++) {
            uint32_t czA = (uint32_t)((((kk << 1) | lcA) ^ swA) * 16);
            uint32_t czB = (uint32_t)((((kk << 1) | lcB) ^ swB) * 16);
            uint32_t adrAhi = stg + SA_HI + (uint32_t)rbA*64 + czA;
            uint32_t adrAlo = stg + SA_LO + (uint32_t)rbA*64 + czA;
            uint32_t adrBhi = stg + SB_HI + (uint32_t)rbB*64 + czB;
            uint32_t adrBlo = stg + SB_LO + (uint32_t)rbB*64 + czB;
            uint32_t fa[4][4], fb[2][4], fbl[2][4];
#pragma unroll
            for (int mt = 0; mt < 4; mt++) ldm4(fa[mt], adrAhi + mt*16*64);
#pragma unroll
            for (int bt = 0; bt < 2; bt++) ldm4(fb[bt], adrBhi + bt*16*64);
#pragma unroll
            for (int mt = 0; mt < 4; mt++)
#pragma unroll
                for (int nt = 0; nt < 4; nt++)
                    mma16816(acc[mt][nt], fa[mt], fb[nt>>1][(nt&1)*2], fb[nt>>1][(nt&1)*2+1]);
#pragma unroll
            for (int bt = 0; bt < 2; bt++) ldm4(fbl[bt], adrBlo + bt*16*64);
#pragma unroll
            for (int mt = 0; mt < 4; mt++)
#pragma unroll
                for (int nt = 0; nt < 4; nt++)
                    mma16816(acc[mt][nt], fa[mt], fbl[nt>>1][(nt&1)*2], fbl[nt>>1][(nt&1)*2+1]);
#pragma unroll
            for (int mt = 0; mt < 4; mt++) ldm4(fa[mt], adrAlo + mt*16*64);
#pragma unroll
            for (int mt = 0; mt < 4; mt++)
#pragma unroll
                for (int nt = 0; nt < 4; nt++)
                    mma16816(acc[mt][nt], fa[mt], fb[nt>>1][(nt&1)*2], fb[nt>>1][(nt&1)*2+1]);
        }
        __syncthreads();
    }

    int mbase = m0 + wm*64 + (lane >> 2);
    int nbase = n0 + wn*32 + (lane & 3)*2;
#pragma unroll
    for (int mt = 0; mt < 4; mt++) {
#pragma unroll
        for (int nt = 0; nt < 4; nt++) {
            int n = nbase + nt*8;
            if (n < N) {
                int m = mbase + mt*16;
                float2 v0 = make_float2(acc[mt][nt][0], acc[mt][nt][1]);
                float2 v1 = make_float2(acc[mt][nt][2], acc[mt][nt][3]);
                float* p0 = &C[(size_t)m * N + n];
                float* p1 = &C[(size_t)(m + 8) * N + n];
                if (beta) {
                    float2 o0 = *(float2*)p0, o1 = *(float2*)p1;
                    v0.x += o0.x; v0.y += o0.y; v1.x += o1.x; v1.y += o1.y;
                }
                *(float2*)p0 = v0;
                *(float2*)p1 = v1;
            }
        }
    }
}

// ---------------- embedding gather (float4) ----------------
__global__ void k_embed(const int* __restrict__ ids, const float* __restrict__ emb,
                        float* __restrict__ h) {
    int i = blockIdx.x * blockDim.x + threadIdx.x;
    if (i >= TOK*DM/4) return;
    int t = i / (DM/4), d4 = i % (DM/4);
    ((float4*)h)[i] = ((const float4*)emb)[(long)ids[t]*(DM/4) + d4];
}

// ---------------- rmsnorm -> bf16 hi/lo (float4) ----------------
__global__ void k_rmsnorm_split(const float* __restrict__ in, const float* __restrict__ w,
                                __nv_bfloat16* __restrict__ ohi, __nv_bfloat16* __restrict__ olo,
                                int D) {
    int row = blockIdx.x;
    const float4* x4 = (const float4*)(in + (long)row*D);
    int nd4 = D >> 2;
    float ss = 0.f;
    for (int d = threadIdx.x; d < nd4; d += blockDim.x) {
        float4 v = x4[d];
        ss += v.x*v.x + v.y*v.y + v.z*v.z + v.w*v.w;
    }
    __shared__ float red[32];
    for (int o = 16; o; o >>= 1) ss += __shfl_down_sync(0xffffffffu, ss, o);
    if ((threadIdx.x & 31) == 0) red[threadIdx.x >> 5] = ss;
    __syncthreads();
    if (threadIdx.x < 32) {
        float v = (threadIdx.x < (blockDim.x >> 5)) ? red[threadIdx.x] : 0.f;
        for (int o = 16; o; o >>= 1) v += __shfl_down_sync(0xffffffffu, v, o);
        if (threadIdx.x == 0) red[0] = rsqrtf(v / (float)D + EPSV);
    }
    __syncthreads();
    float s = red[0];
    const float4* w4 = (const float4*)w;
    uint2* h2 = (uint2*)(ohi + (long)row*D);
    uint2* l2 = (uint2*)(olo + (long)row*D);
    for (int d = threadIdx.x; d < nd4; d += blockDim.x) {
        float4 v = x4[d], ww = w4[d];
        v.x *= s*ww.x; v.y *= s*ww.y; v.z *= s*ww.z; v.w *= s*ww.w;
        uint2 h, l;
        split2(v.x, v.y, h.x, l.x);
        split2(v.z, v.w, h.y, l.y);
        h2[d] = h; l2[d] = l;
    }
}

// ---------------- plain rmsnorm (final, float4) ----------------
__global__ void k_rmsnorm(const float* __restrict__ in, const float* __restrict__ w,
                          float* __restrict__ out, int D) {
    int row = blockIdx.x;
    const float4* x4 = (const float4*)(in + (long)row*D);
    int nd4 = D >> 2;
    float ss = 0.f;
    for (int d = threadIdx.x; d < nd4; d += blockDim.x) {
        float4 v = x4[d];
        ss += v.x*v.x + v.y*v.y + v.z*v.z + v.w*v.w;
    }
    __shared__ float red[32];
    for (int o = 16; o; o >>= 1) ss += __shfl_down_sync(0xffffffffu, ss, o);
    if ((threadIdx.x & 31) == 0) red[threadIdx.x >> 5] = ss;
    __syncthreads();
    if (threadIdx.x < 32) {
        float v = (threadIdx.x < (blockDim.x >> 5)) ? red[threadIdx.x] : 0.f;
        for (int o = 16; o; o >>= 1) v += __shfl_down_sync(0xffffffffu, v, o);
        if (threadIdx.x == 0) red[0] = rsqrtf(v / (float)D + EPSV);
    }
    __syncthreads();
    float s = red[0];
    const float4* w4 = (const float4*)w;
    float4* o4 = (float4*)(out + (long)row*D);
    for (int d = threadIdx.x; d < nd4; d += blockDim.x) {
        float4 v = x4[d], ww = w4[d];
        v.x *= s*ww.x; v.y *= s*ww.y; v.z *= s*ww.z; v.w *= s*ww.w;
        o4[d] = v;
    }
}

// ---------------- fused conv+silu and dt=softplus ----------------
__global__ void k_convdt(const float* __restrict__ zx, const float* __restrict__ w,
                         const float* __restrict__ bconv, const float* __restrict__ dtb,
                         float* __restrict__ xBC, float* __restrict__ dtout) {
    int i = blockIdx.x * blockDim.x + threadIdx.x;
    if (i < TOK*CONVD) {
        int c = i % CONVD;
        int t = i / CONVD;
        int s = t % SEQL;
        const float* src = zx + (long)t*DIP + DI + c;
        float acc = bconv[c];
#pragma unroll
        for (int k = 0; k < KC; k++) {
            int ss = s - (KC-1) + k;
            if (ss >= 0) acc += w[c*KC + k] * src[(long)(ss - s) * DIP];
        }
        xBC[i] = acc / (1.f + expf(-acc));
    } else {
        int j = i - TOK*CONVD;
        if (j >= TOK*NH) return;
        int h = j % NH, t = j / NH;
        float v = zx[(long)t*DIP + DI + CONVD + h] + dtb[h];
        dtout[j] = (v > 20.f) ? v : log1pf(expf(v));
    }
}

// ---------------- SSD scan: p-split, 2 CTAs per (b,h), 128 threads ----------------
// stage floats: B0:0 C0:128 B1:256 C1:384 x0:512(32) x1:544(32) dt:576,577 pad->592
#define SC_STGF 592
#define SC_STGB (SC_STGF*4)
__global__ void __launch_bounds__(128, 4) k_scan(
        const float* __restrict__ xBC, const float* __restrict__ dt,
        const float* __restrict__ A_log, const float* __restrict__ Dvec,
        float* __restrict__ y) {
    int blk = blockIdx.x;
    int ph = blk & 1;               // p half: rows ph*32 .. +31
    int bh = blk >> 1;
    int b = bh / NH;
    int h = bh % NH;
    float A = -expf(A_log[h]);
    float Dh = Dvec[h];
    int tid = threadIdx.x;          // 128
    int pi = tid >> 4;              // 0..7 -> 4 p-rows each
    int ni = tid & 15;              // 0..15 -> 8 n each

    __shared__ __align__(16) float ring[4*SC_STGF];
    uint32_t rb = smem_u32(ring);
    const float* base = xBC + (long)b*SEQL*CONVD;
    const float* dbase = dt + ((long)b*SEQL)*NH + h;
    int xoff = h*HD + ph*32;

    u64t st2[4][4];
#pragma unroll
    for (int i = 0; i < 4; i++)
#pragma unroll
        for (int j = 0; j < 4; j++) st2[i][j] = 0ULL;

    auto issue = [&](int s) {
        uint32_t sa = rb + (uint32_t)(s & 3) * SC_STGB;
        const float* r0 = base + (long)(2*s) * CONVD;
        const float* r1 = r0 + CONVD;
        if (tid < 32)       cp16(sa +            tid*16,      r0 + DI + tid*4, 16);            // B0
        else if (tid < 64)  cp16(sa + 512  + (tid-32)*16,     r0 + DI + DS + (tid-32)*4, 16);  // C0
        else if (tid < 96)  cp16(sa + 1024 + (tid-64)*16,     r1 + DI + (tid-64)*4, 16);       // B1
        else                cp16(sa + 1536 + (tid-96)*16,     r1 + DI + DS + (tid-96)*4, 16);  // C1
        if (tid < 8)        cp16(sa + 2048 + tid*16,          r0 + xoff + tid*4, 16);          // x0
        else if (tid < 16)  cp16(sa + 2176 + (tid-8)*16,      r1 + xoff + (tid-8)*4, 16);      // x1
        else if (tid == 16) cp4(sa + 2304, dbase + (long)(2*s)*NH);
        else if (tid == 17) cp4(sa + 2308, dbase + (long)(2*s+1)*NH);
        CP_COMMIT();
    };

    issue(0); issue(1); issue(2); issue(3);

    const int NPAIR = SEQL/2;
    for (int s = 0; s < NPAIR; s++) {
        CP_WAIT3();
        __syncthreads();
        const float* stg = ring + (s & 3) * SC_STGF;
#pragma unroll
        for (int half = 0; half < 2; half++) {
            int t = 2*s + half;
            float dtt = stg[576 + half];
            float decay = expf(dtt * A);
            u64t decay2 = pk2(decay, decay);
            u64t dt2 = pk2(dtt, dtt);
            const float* Bp = stg + half*256;
            const float* Cp = Bp + 128;
            u64t B2[4], C2[4];
            {
                ulonglong2 bb0 = *(const ulonglong2*)&Bp[ni*8];
                ulonglong2 bb1 = *(const ulonglong2*)&Bp[ni*8 + 4];
                B2[0] = bb0.x; B2[1] = bb0.y; B2[2] = bb1.x; B2[3] = bb1.y;
                ulonglong2 cc0 = *(const ulonglong2*)&Cp[ni*8];
                ulonglong2 cc1 = *(const ulonglong2*)&Cp[ni*8 + 4];
                C2[0] = cc0.x; C2[1] = cc0.y; C2[2] = cc1.x; C2[3] = cc1.y;
            }
            u64t dtB2[4];
#pragma unroll
            for (int j = 0; j < 4; j++) dtB2[j] = mul2_(dt2, B2[j]);
            const float* xp = stg + 512 + half*32;
            float vout[4];
#pragma unroll
            for (int pp = 0; pp < 4; pp++) {
                float xv = xp[pi*4 + pp];
                u64t x2 = pk2(xv, xv);
                u64t acc2 = 0ULL;
#pragma unroll
                for (int j = 0; j < 4; j++) {
                    st2[pp][j] = fma2_(st2[pp][j], decay2, mul2_(x2, dtB2[j]));
                    acc2 = fma2_(st2[pp][j], C2[j], acc2);
                }
                float a0, a1;
                upk2(acc2, a0, a1);
                float a = a0 + a1;
                a += __shfl_down_sync(0xffffffffu, a, 8, 16);
                a += __shfl_down_sync(0xffffffffu, a, 4, 16);
                a += __shfl_down_sync(0xffffffffu, a, 2, 16);
                a += __shfl_down_sync(0xffffffffu, a, 1, 16);
                vout[pp] = a + Dh * xv;
            }
            if (ni == 0) {
                float4 v = make_float4(vout[0], vout[1], vout[2], vout[3]);
                *(float4*)&y[((long)b*SEQL + t)*DI + xoff + pi*4] = v;
            }
        }
        __syncthreads();
        if (s + 4 < NPAIR) issue(s + 4);
        else CP_COMMIT();
    }
}

// ---------------- y = rmsnorm(y * silu(z)) * w -> bf16 hi/lo (float4) ----------------
__global__ void k_gatenorm_split(const float* __restrict__ yin, const float* __restrict__ zx,
                                 const float* __restrict__ w,
                                 __nv_bfloat16* __restrict__ ohi, __nv_bfloat16* __restrict__ olo) {
    int row = blockIdx.x;
    const float4* yr = (const float4*)(yin + (long)row*DI);
    const float4* zr = (const float4*)(zx + (long)row*DIP);
    __shared__ __align__(16) float sv[DI];
    float ss = 0.f;
    const int nd4 = DI >> 2;
    for (int d = threadIdx.x; d < nd4; d += blockDim.x) {
        float4 zv = zr[d], yv = yr[d];
        float4 v;
        v.x = yv.x * (zv.x / (1.f + expf(-zv.x)));
        v.y = yv.y * (zv.y / (1.f + expf(-zv.y)));
        v.z = yv.z * (zv.z / (1.f + expf(-zv.z)));
        v.w = yv.w * (zv.w / (1.f + expf(-zv.w)));
        ((float4*)sv)[d] = v;
        ss += v.x*v.x + v.y*v.y + v.z*v.z + v.w*v.w;
    }
    __shared__ float red[32];
    for (int o = 16; o; o >>= 1) ss += __shfl_down_sync(0xffffffffu, ss, o);
    if ((threadIdx.x & 31) == 0) red[threadIdx.x >> 5] = ss;
    __syncthreads();
    if (threadIdx.x < 32) {
        float v = (threadIdx.x < (blockDim.x >> 5)) ? red[threadIdx.x] : 0.f;
        for (int o = 16; o; o >>= 1) v += __shfl_down_sync(0xffffffffu, v, o);
        if (threadIdx.x == 0) red[0] = rsqrtf(v / (float)DI + EPSV);
    }
    __syncthreads();
    float s = red[0];
    const float4* w4 = (const float4*)w;
    uint2* h2 = (uint2*)(ohi + (long)row*DI);
    uint2* l2 = (uint2*)(olo + (long)row*DI);
    for (int d = threadIdx.x; d < nd4; d += blockDim.x) {
        float4 v = ((float4*)sv)[d], ww = w4[d];
        v.x *= s*ww.x; v.y *= s*ww.y; v.z *= s*ww.z; v.w *= s*ww.w;
        uint2 h, l;
        split2(v.x, v.y, h.x, l.x);
        split2(v.z, v.w, h.y, l.y);
        h2[d] = h; l2[d] = l;
    }
}

// ---------------- masked mean pool + cat embed concat ----------------
__global__ void k_pool(const float* __restrict__ x, const int* __restrict__ mask,
                       const int* __restrict__ cats, const float* __restrict__ cat_emb,
                       float* __restrict__ feat) {
    int b = blockIdx.x;
    __shared__ float sm[SEQL];
    __shared__ float minv;
    for (int t = threadIdx.x; t < SEQL; t += blockDim.x)
        sm[t] = (float)mask[b*SEQL + t];
    __syncthreads();
    if (threadIdx.x == 0) {
        float s = 0.f;
        for (int t = 0; t < SEQL; t++) s += sm[t];
        if (s < 1e-9f) s = 1e-9f;
        minv = 1.f / s;
    }
    __syncthreads();
    for (int d = threadIdx.x; d < DM; d += blockDim.x) {
        float acc = 0.f;
        for (int t = 0; t < SEQL; t++)
            acc += sm[t] * x[((long)b*SEQL + t)*DM + d];
        feat[b*FEATD + d] = acc * minv;
    }
    if (threadIdx.x < 16)
        feat[b*FEATD + DM + threadIdx.x] = cat_emb[cats[b]*16 + threadIdx.x];
}

// ---------------- classifier heads ----------------
__global__ void k_heads(const float* __restrict__ feat,
                        const float* __restrict__ qw, const float* __restrict__ qb,
                        const float* __restrict__ aw, const float* __restrict__ ab,
                        float* __restrict__ out) {
    int b = blockIdx.y, j = blockIdx.x;
    const float* w;
    float bias;
    if (j < 21) { w = qw + j*FEATD; bias = qb[j]; }
    else        { w = aw + (j-21)*FEATD; bias = ab[j-21]; }
    float s = 0.f;
    for (int d = threadIdx.x; d < FEATD; d += blockDim.x)
        s += feat[b*FEATD + d] * w[d];
    __shared__ float red[8];
    for (int o = 16; o; o >>= 1) s += __shfl_down_sync(0xffffffffu, s, o);
    if ((threadIdx.x & 31) == 0) red[threadIdx.x >> 5] = s;
    __syncthreads();
    if (threadIdx.x == 0) {
        float v = 0.f;
        for (int i = 0; i < (int)(blockDim.x >> 5); i++) v += red[i];
        out[b*30 + j] = v + bias;
    }
}

// ---------------- host orchestration ----------------
extern "C" void kernel_launch(void* const* d_in, const int* in_sizes, int n_in,
                              void* d_out, int out_size) {
    const int*   ids      = (const int*)d_in[0];
    const int*   mask     = (const int*)d_in[1];
    const int*   cats     = (const int*)d_in[2];
    const float* emb      = (const float*)d_in[3];
    const float* norm_w   = (const float*)d_in[4];
    const float* in_proj  = (const float*)d_in[5];
    const float* conv_w   = (const float*)d_in[6];
    const float* conv_b   = (const float*)d_in[7];
    const float* dt_bias  = (const float*)d_in[8];
    const float* A_log    = (const float*)d_in[9];
    const float* Dvec     = (const float*)d_in[10];
    const float* gnorm_w  = (const float*)d_in[11];
    const float* out_proj = (const float*)d_in[12];
    const float* final_w  = (const float*)d_in[13];
    const float* cat_emb  = (const float*)d_in[14];
    const float* qw       = (const float*)d_in[15];
    const float* qb       = (const float*)d_in[16];
    const float* aw       = (const float*)d_in[17];
    const float* ab       = (const float*)d_in[18];
    float* out = (float*)d_out;

    float *p_h, *p_x, *p_zx, *p_xBC, *p_dt, *p_y, *p_feat;
    __nv_bfloat16 *p_wihi, *p_wilo, *p_wohi, *p_wolo, *p_ahi, *p_alo;
    cudaGetSymbolAddress((void**)&p_h,    g_h);
    cudaGetSymbolAddress((void**)&p_x,    g_x);
    cudaGetSymbolAddress((void**)&p_zx,   g_zx);
    cudaGetSymbolAddress((void**)&p_xBC,  g_xBC);
    cudaGetSymbolAddress((void**)&p_dt,   g_dt);
    cudaGetSymbolAddress((void**)&p_y,    g_y);
    cudaGetSymbolAddress((void**)&p_feat, g_feat);
    cudaGetSymbolAddress((void**)&p_wihi, g_wihi);
    cudaGetSymbolAddress((void**)&p_wilo, g_wilo);
    cudaGetSymbolAddress((void**)&p_wohi, g_wohi);
    cudaGetSymbolAddress((void**)&p_wolo, g_wolo);
    cudaGetSymbolAddress((void**)&p_ahi,  g_ahi);
    cudaGetSymbolAddress((void**)&p_alo,  g_alo);

    cudaFuncSetAttribute(k_gemm_mma, cudaFuncAttributeMaxDynamicSharedMemorySize, GEMM_SMEM);

    {
        long ntot = NIN4 + NOUT4;
        k_split_all<<<(unsigned)((ntot + 255)/256), 256>>>(
            (const float4*)in_proj, (const float4*)out_proj,
            (uint2*)p_wihi, (uint2*)p_wilo, (uint2*)p_wohi, (uint2*)p_wolo);
    }
    {
        int n = TOK*DM/4;
        k_embed<<<(n + 255)/256, 256>>>(ids, emb, p_h);
    }

    for (int l = 0; l < NL; l++) {
        k_rmsnorm_split<<<TOK, 256>>>(p_h, norm_w + l*DM, p_ahi, p_alo, DM);
        {
            dim3 grid(TOK/128, (DIP + 63)/64);
            k_gemm_mma<<<grid, 128, GEMM_SMEM>>>(p_ahi, p_alo,
                                                 p_wihi + (long)l*DIP*DM, p_wilo + (long)l*DIP*DM,
                                                 p_zx, DIP, DM, 0);
        }
        {
            int n = TOK*CONVD + TOK*NH;
            k_convdt<<<(n + 255)/256, 256>>>(p_zx, conv_w + (long)l*CONVD*KC,
                                             conv_b + l*CONVD, dt_bias + l*NH,
                                             p_xBC, p_dt);
        }
        k_scan<<<BATCH*NH*2, 128>>>(p_xBC, p_dt, A_log + l*NH, Dvec + l*NH, p_y);
        k_gatenorm_split<<<TOK, 256>>>(p_y, p_zx, gnorm_w + (long)l*DI, p_ahi, p_alo);
        {
            dim3 grid(TOK/128, DM/64);
            k_gemm_mma<<<grid, 128, GEMM_SMEM>>>(p_ahi, p_alo,
                                                 p_wohi + (long)l*DM*DI, p_wolo + (long)l*DM*DI,
                                                 p_h, DM, DI, 1);
        }
    }

    k_rmsnorm<<<TOK, 256>>>(p_h, final_w, p_x, DM);
    k_pool<<<BATCH, 256>>>(p_x, mask, cats, cat_emb, p_feat);
    {
        dim3 grid(30, BATCH);
        k_heads<<<grid, 128>>>(p_feat, qw, qb, aw, ab, out);
    }
}